// round 1
// baseline (speedup 1.0000x reference)
#include <cuda_runtime.h>
#include <cstdint>

// Problem constants
#define B_ 8
#define T_ 4096
#define C_ 1024
#define H_ 128
#define M_ (B_ * T_)   // 32768 rows

// Scratch for q,k,v projections (device globals: allocation-free rule)
__device__ float g_q[(size_t)M_ * H_];
__device__ float g_k[(size_t)M_ * H_];
__device__ float g_v[(size_t)M_ * H_];

// ---------------------------------------------------------------------------
// Kernel A: fused QKV projection.  out[m,h] = sum_c x[m,c] * W[h,c]
// Tile 128x128x16, 256 threads, 8x8 microtile per thread.
// gridDim.x = M/128 = 256, gridDim.y = 3 (0:q scaled, 1:k, 2:v)
// ---------------------------------------------------------------------------
__global__ __launch_bounds__(256) void qkv_kernel(
    const float* __restrict__ x,
    const float* __restrict__ Wk,
    const float* __restrict__ Wq,
    const float* __restrict__ Wv)
{
    __shared__ float sX[16 * 132];   // sX[k][m], padded rows
    __shared__ float sW[16 * 132];   // sW[k][n]

    const int m0  = blockIdx.x * 128;
    const int sel = blockIdx.y;
    const float* W   = (sel == 0) ? Wq  : (sel == 1) ? Wk  : Wv;
    float*       out = (sel == 0) ? g_q : (sel == 1) ? g_k : g_v;
    const float scl  = (sel == 0) ? 0.08838834764831845f : 1.0f;  // 1/sqrt(128)

    const int tid = threadIdx.x;
    const int tx  = tid & 15;   // 16 wide
    const int ty  = tid >> 4;   // 16 tall

    float acc[8][8];
#pragma unroll
    for (int i = 0; i < 8; i++)
#pragma unroll
        for (int j = 0; j < 8; j++) acc[i][j] = 0.f;

    for (int kt = 0; kt < C_ / 16; kt++) {
        const int k0 = kt * 16;
        // Load 128x16 tiles of x and W, transposed into smem.
#pragma unroll
        for (int it = 0; it < 2; it++) {
            int s  = tid + it * 256;       // 0..511 float4 slots
            int m  = s >> 2;               // 0..127
            int k4 = (s & 3) * 4;          // 0,4,8,12
            float4 vx = *(const float4*)(x + (size_t)(m0 + m) * C_ + k0 + k4);
            sX[(k4 + 0) * 132 + m] = vx.x;
            sX[(k4 + 1) * 132 + m] = vx.y;
            sX[(k4 + 2) * 132 + m] = vx.z;
            sX[(k4 + 3) * 132 + m] = vx.w;
            float4 vw = *(const float4*)(W + (size_t)m * C_ + k0 + k4);  // n == m slot
            sW[(k4 + 0) * 132 + m] = vw.x;
            sW[(k4 + 1) * 132 + m] = vw.y;
            sW[(k4 + 2) * 132 + m] = vw.z;
            sW[(k4 + 3) * 132 + m] = vw.w;
        }
        __syncthreads();

#pragma unroll
        for (int kk = 0; kk < 16; kk++) {
            float a[8], bb[8];
#pragma unroll
            for (int i = 0; i < 8; i++) a[i]  = sX[kk * 132 + ty * 8 + i];   // broadcast
#pragma unroll
            for (int j = 0; j < 8; j++) bb[j] = sW[kk * 132 + tx + 16 * j];  // conflict-free
#pragma unroll
            for (int i = 0; i < 8; i++)
#pragma unroll
                for (int j = 0; j < 8; j++)
                    acc[i][j] = fmaf(a[i], bb[j], acc[i][j]);
        }
        __syncthreads();
    }

#pragma unroll
    for (int i = 0; i < 8; i++) {
        const size_t row = (size_t)(m0 + ty * 8 + i);
#pragma unroll
        for (int j = 0; j < 8; j++)
            out[row * H_ + tx + 16 * j] = acc[i][j] * scl;
    }
}

// ---------------------------------------------------------------------------
// Kernel B: causal flash attention, fp32.
// One block = 64 q-rows of one batch. 256 threads (16x16).
// Thread (ty,tx): S-frag rows ty*4+i, cols tx+16*j (j<4);
//                 O-frag rows ty*4+i, head cols tx+16*j (j<8).
// ---------------------------------------------------------------------------
#define FLASH_SMEM_FLOATS (64 * 128 + 64 * 132 + 64 * 128 + 64 * 65)
#define FLASH_SMEM_BYTES  (FLASH_SMEM_FLOATS * 4)

__global__ __launch_bounds__(256) void flash_kernel(float* __restrict__ out)
{
    extern __shared__ float sm[];
    float* sQ = sm;                    // [64][128]
    float* sK = sQ + 64 * 128;         // [64][132]  (padded: breaks stride-128 conflicts)
    float* sV = sK + 64 * 132;         // [64][128]
    float* sP = sV + 64 * 128;         // [64][65]

    const int b   = blockIdx.y;
    const int r0  = blockIdx.x * 64;
    const int tid = threadIdx.x;
    const int tx  = tid & 15;
    const int ty  = tid >> 4;

    // Load Q tile (contiguous rows -> linear vector copy)
    const float* qbase = g_q + ((size_t)b * T_ + r0) * H_;
#pragma unroll
    for (int it = 0; it < 8; it++) {
        int s = tid + it * 256;
        ((float4*)sQ)[s] = ((const float4*)qbase)[s];
    }

    float m_i[4], l_i[4], acc[4][8];
#pragma unroll
    for (int i = 0; i < 4; i++) { m_i[i] = -1e30f; l_i[i] = 0.f; }
#pragma unroll
    for (int i = 0; i < 4; i++)
#pragma unroll
        for (int j = 0; j < 8; j++) acc[i][j] = 0.f;

    for (int s0 = 0; s0 <= r0; s0 += 64) {
        __syncthreads();   // previous PV reads of sK/sV done
        const float* kbase = g_k + ((size_t)b * T_ + s0) * H_;
        const float* vbase = g_v + ((size_t)b * T_ + s0) * H_;
#pragma unroll
        for (int it = 0; it < 8; it++) {
            int s  = tid + it * 256;
            int r  = s >> 5;           // row 0..63
            int c4 = (s & 31) * 4;     // col 0..124
            *(float4*)(sK + r * 132 + c4) = *(const float4*)(kbase + (size_t)r * H_ + c4);
            ((float4*)sV)[s] = ((const float4*)vbase)[s];
        }
        __syncthreads();

        // S = Q K^T  (q pre-scaled by 1/sqrt(H))
        float sf[4][4];
#pragma unroll
        for (int i = 0; i < 4; i++)
#pragma unroll
            for (int j = 0; j < 4; j++) sf[i][j] = 0.f;

#pragma unroll 4
        for (int k = 0; k < 128; k++) {
            float a[4], bb[4];
#pragma unroll
            for (int i = 0; i < 4; i++) a[i]  = sQ[(ty * 4 + i) * 128 + k];     // broadcast
#pragma unroll
            for (int j = 0; j < 4; j++) bb[j] = sK[(tx + 16 * j) * 132 + k];    // 2-way max
#pragma unroll
            for (int i = 0; i < 4; i++)
#pragma unroll
                for (int j = 0; j < 4; j++)
                    sf[i][j] = fmaf(a[i], bb[j], sf[i][j]);
        }

        // causal mask only needed on the diagonal tile
        if (s0 == r0) {
#pragma unroll
            for (int i = 0; i < 4; i++)
#pragma unroll
                for (int j = 0; j < 4; j++)
                    if (s0 + tx + 16 * j > r0 + ty * 4 + i) sf[i][j] = -1e30f;
        }

        // online softmax per row (16-lane butterfly within warp halves)
#pragma unroll
        for (int i = 0; i < 4; i++) {
            float v = sf[i][0];
#pragma unroll
            for (int j = 1; j < 4; j++) v = fmaxf(v, sf[i][j]);
#pragma unroll
            for (int m = 1; m < 16; m <<= 1)
                v = fmaxf(v, __shfl_xor_sync(0xffffffffu, v, m));
            const float mn  = fmaxf(m_i[i], v);
            const float fac = __expf(m_i[i] - mn);
            m_i[i] = mn;
            float rs = 0.f;
#pragma unroll
            for (int j = 0; j < 4; j++) {
                float p = __expf(sf[i][j] - mn);
                sf[i][j] = p;
                rs += p;
            }
#pragma unroll
            for (int m = 1; m < 16; m <<= 1)
                rs += __shfl_xor_sync(0xffffffffu, rs, m);
            l_i[i] = l_i[i] * fac + rs;
#pragma unroll
            for (int j = 0; j < 4; j++)
                sP[(ty * 4 + i) * 65 + tx + 16 * j] = sf[i][j];
#pragma unroll
            for (int j = 0; j < 8; j++) acc[i][j] *= fac;
        }
        __syncthreads();

        // O += P @ V
#pragma unroll 2
        for (int k = 0; k < 64; k++) {
            float p[4], vv[8];
#pragma unroll
            for (int i = 0; i < 4; i++) p[i]  = sP[(ty * 4 + i) * 65 + k];   // broadcast
#pragma unroll
            for (int j = 0; j < 8; j++) vv[j] = sV[k * 128 + tx + 16 * j];   // conflict-free
#pragma unroll
            for (int i = 0; i < 4; i++)
#pragma unroll
                for (int j = 0; j < 8; j++)
                    acc[i][j] = fmaf(p[i], vv[j], acc[i][j]);
        }
    }

    float* ob = out + ((size_t)b * T_ + r0) * H_;
#pragma unroll
    for (int i = 0; i < 4; i++) {
        const float inv = 1.0f / l_i[i];
#pragma unroll
        for (int j = 0; j < 8; j++)
            ob[(size_t)(ty * 4 + i) * H_ + tx + 16 * j] = acc[i][j] * inv;
    }
}

// ---------------------------------------------------------------------------
extern "C" void kernel_launch(void* const* d_in, const int* in_sizes, int n_in,
                              void* d_out, int out_size)
{
    const float* x  = (const float*)d_in[0];
    const float* Wk = (const float*)d_in[1];
    const float* Wq = (const float*)d_in[2];
    const float* Wv = (const float*)d_in[3];
    float* out = (float*)d_out;

    cudaFuncSetAttribute(flash_kernel,
                         cudaFuncAttributeMaxDynamicSharedMemorySize,
                         FLASH_SMEM_BYTES);

    qkv_kernel<<<dim3(M_ / 128, 3, 1), 256>>>(x, Wk, Wq, Wv);
    flash_kernel<<<dim3(T_ / 64, B_, 1), 256, FLASH_SMEM_BYTES>>>(out);
}

// round 3
// speedup vs baseline: 2.4590x; 2.4590x over previous
#include <cuda_runtime.h>
#include <cuda_bf16.h>
#include <cstdint>

#define B_ 8
#define T_ 4096
#define C_ 1024
#define H_ 128
#define M_ (B_ * T_)   // 32768

// ---------------- device scratch (allocation-free rule) ----------------
__device__ __nv_bfloat16 g_xh[(size_t)M_ * C_];
__device__ __nv_bfloat16 g_xl[(size_t)M_ * C_];
__device__ __nv_bfloat16 g_wh[3][(size_t)H_ * C_];
__device__ __nv_bfloat16 g_wl[3][(size_t)H_ * C_];
__device__ __nv_bfloat16 g_qh[(size_t)M_ * H_], g_ql[(size_t)M_ * H_];
__device__ __nv_bfloat16 g_kh[(size_t)M_ * H_], g_kl[(size_t)M_ * H_];
__device__ __nv_bfloat16 g_vh[(size_t)M_ * H_], g_vl[(size_t)M_ * H_];

// ---------------- helpers ----------------
__device__ __forceinline__ uint32_t smem_u32(const void* p) {
    uint32_t a;
    asm("{ .reg .u64 t; cvta.to.shared.u64 t, %1; cvt.u32.u64 %0, t; }"
        : "=r"(a) : "l"(p));
    return a;
}
__device__ __forceinline__ void ldsm4(uint32_t r[4], uint32_t a) {
    asm volatile("ldmatrix.sync.aligned.m8n8.x4.shared.b16 {%0,%1,%2,%3}, [%4];"
        : "=r"(r[0]), "=r"(r[1]), "=r"(r[2]), "=r"(r[3]) : "r"(a));
}
__device__ __forceinline__ void ldsm4t(uint32_t r[4], uint32_t a) {
    asm volatile("ldmatrix.sync.aligned.m8n8.x4.trans.shared.b16 {%0,%1,%2,%3}, [%4];"
        : "=r"(r[0]), "=r"(r[1]), "=r"(r[2]), "=r"(r[3]) : "r"(a));
}
__device__ __forceinline__ void mma16816(float c[4], const uint32_t a[4],
                                         uint32_t b0, uint32_t b1) {
    asm volatile(
        "mma.sync.aligned.m16n8k16.row.col.f32.bf16.bf16.f32 "
        "{%0,%1,%2,%3}, {%4,%5,%6,%7}, {%8,%9}, {%0,%1,%2,%3};"
        : "+f"(c[0]), "+f"(c[1]), "+f"(c[2]), "+f"(c[3])
        : "r"(a[0]), "r"(a[1]), "r"(a[2]), "r"(a[3]), "r"(b0), "r"(b1));
}
// split fp32 pair into (hi bf16x2, lo bf16x2)
__device__ __forceinline__ uint32_t split_pack(float v0, float v1, uint32_t& lo) {
    __nv_bfloat16 h0 = __float2bfloat16(v0), h1 = __float2bfloat16(v1);
    __nv_bfloat16 l0 = __float2bfloat16(v0 - __bfloat162float(h0));
    __nv_bfloat16 l1 = __float2bfloat16(v1 - __bfloat162float(h1));
    __nv_bfloat162 L(l0, l1), Hh(h0, h1);
    lo = *reinterpret_cast<uint32_t*>(&L);
    return *reinterpret_cast<uint32_t*>(&Hh);
}

// ---------------- fp32 -> bf16 hi/lo conversions ----------------
__global__ __launch_bounds__(256) void convert_x_kernel(const float* __restrict__ x)
{
    size_t i = (size_t)blockIdx.x * 256 + threadIdx.x;
    float4 v = ((const float4*)x)[i];
    uint32_t l01, l23;
    uint32_t h01 = split_pack(v.x, v.y, l01);
    uint32_t h23 = split_pack(v.z, v.w, l23);
    ((uint32_t*)g_xh)[2 * i + 0] = h01; ((uint32_t*)g_xh)[2 * i + 1] = h23;
    ((uint32_t*)g_xl)[2 * i + 0] = l01; ((uint32_t*)g_xl)[2 * i + 1] = l23;
}
__global__ __launch_bounds__(256) void convert_w_kernel(
    const float* __restrict__ Wk, const float* __restrict__ Wq,
    const float* __restrict__ Wv)
{
    const int sel = blockIdx.y;
    const float* W = (sel == 0) ? Wq : (sel == 1) ? Wk : Wv;
    size_t i = (size_t)blockIdx.x * 256 + threadIdx.x;
    float4 v = ((const float4*)W)[i];
    uint32_t l01, l23;
    uint32_t h01 = split_pack(v.x, v.y, l01);
    uint32_t h23 = split_pack(v.z, v.w, l23);
    ((uint32_t*)g_wh[sel])[2 * i + 0] = h01; ((uint32_t*)g_wh[sel])[2 * i + 1] = h23;
    ((uint32_t*)g_wl[sel])[2 * i + 0] = l01; ((uint32_t*)g_wl[sel])[2 * i + 1] = l23;
}

// ---------------- QKV projection: mma.sync bf16x3 ----------------
// grid (M_/128, 3); 256 threads (8 warps x 16 rows). K chunks of 64.
#define PSTR 72
#define P_SMEM (4 * 128 * PSTR * 2)

__global__ __launch_bounds__(256) void qkv_mma_kernel()
{
    extern __shared__ __nv_bfloat16 ps[];
    __nv_bfloat16* sxh = ps;
    __nv_bfloat16* sxl = sxh + 128 * PSTR;
    __nv_bfloat16* swh = sxl + 128 * PSTR;
    __nv_bfloat16* swl = swh + 128 * PSTR;

    const int tid = threadIdx.x, lane = tid & 31, w = tid >> 5;
    const int sel = blockIdx.y;
    const int m0  = blockIdx.x * 128;
    const int wr0 = w * 16;

    const __nv_bfloat16* xh = g_xh + (size_t)m0 * C_;
    const __nv_bfloat16* xl = g_xl + (size_t)m0 * C_;
    const __nv_bfloat16* wh = g_wh[sel];
    const __nv_bfloat16* wl = g_wl[sel];

    float of[16][4];
#pragma unroll
    for (int j = 0; j < 16; j++)
#pragma unroll
        for (int e = 0; e < 4; e++) of[j][e] = 0.f;

    // per-thread ldsm byte offsets
    const uint32_t a_off = (uint32_t)(wr0 + (lane & 15)) * (PSTR * 2) + (lane >> 4) * 16;
    const uint32_t b_off = (uint32_t)((lane & 7) + ((lane >> 4) & 1) * 8) * (PSTR * 2)
                         + ((lane >> 3) & 1) * 16;
    const uint32_t sxh_b = smem_u32(sxh), sxl_b = smem_u32(sxl);
    const uint32_t swh_b = smem_u32(swh), swl_b = smem_u32(swl);

    for (int kc = 0; kc < C_ / 64; kc++) {
        __syncthreads();
        const int k0 = kc * 64;
#pragma unroll
        for (int it = 0; it < 4; it++) {
            int i = tid + it * 256;           // 1024 uint4 per array
            int row = i >> 3, c8 = (i & 7) * 8;
            *(uint4*)&sxh[row * PSTR + c8] = *(const uint4*)&xh[(size_t)row * C_ + k0 + c8];
            *(uint4*)&sxl[row * PSTR + c8] = *(const uint4*)&xl[(size_t)row * C_ + k0 + c8];
            *(uint4*)&swh[row * PSTR + c8] = *(const uint4*)&wh[(size_t)row * C_ + k0 + c8];
            *(uint4*)&swl[row * PSTR + c8] = *(const uint4*)&wl[(size_t)row * C_ + k0 + c8];
        }
        __syncthreads();

#pragma unroll
        for (int u = 0; u < 4; u++) {
            uint32_t axh[4], axl[4];
            ldsm4(axh, sxh_b + a_off + u * 32);
            ldsm4(axl, sxl_b + a_off + u * 32);
#pragma unroll
            for (int jp = 0; jp < 8; jp++) {
                uint32_t bh[4], bl[4];
                const uint32_t o = b_off + (uint32_t)jp * 16 * (PSTR * 2) + u * 32;
                ldsm4(bh, swh_b + o);
                ldsm4(bl, swl_b + o);
                mma16816(of[2 * jp],     axh, bh[0], bh[1]);
                mma16816(of[2 * jp],     axh, bl[0], bl[1]);
                mma16816(of[2 * jp],     axl, bh[0], bh[1]);
                mma16816(of[2 * jp + 1], axh, bh[2], bh[3]);
                mma16816(of[2 * jp + 1], axh, bl[2], bl[3]);
                mma16816(of[2 * jp + 1], axl, bh[2], bh[3]);
            }
        }
    }

    const float scl = (sel == 0) ? 0.08838834764831845f : 1.0f;   // q: 1/sqrt(128)
    __nv_bfloat16* oh = (sel == 0) ? g_qh : (sel == 1) ? g_kh : g_vh;
    __nv_bfloat16* ol = (sel == 0) ? g_ql : (sel == 1) ? g_kl : g_vl;
#pragma unroll
    for (int j = 0; j < 16; j++)
#pragma unroll
        for (int i = 0; i < 2; i++) {
            const size_t row = (size_t)(m0 + wr0 + (lane >> 2) + 8 * i);
            const int col = 8 * j + (lane & 3) * 2;
            uint32_t lo;
            uint32_t hi = split_pack(of[j][2 * i] * scl, of[j][2 * i + 1] * scl, lo);
            *(uint32_t*)&oh[row * H_ + col] = hi;
            *(uint32_t*)&ol[row * H_ + col] = lo;
        }
}

// ---------------- flash attention: mma.sync bf16x3 ----------------
// BM=128 q rows/block, BN=64 kv/iter. 8 warps x 16 q rows.
#define FSTR 136
#define F_SMEM ((2 * 128 + 4 * 64) * FSTR * 2)   // 139264 B

__global__ __launch_bounds__(256) void flash_kernel(float* __restrict__ out)
{
    extern __shared__ __nv_bfloat16 fs[];
    __nv_bfloat16* sqh = fs;
    __nv_bfloat16* sql = sqh + 128 * FSTR;
    __nv_bfloat16* skh = sql + 128 * FSTR;
    __nv_bfloat16* skl = skh + 64 * FSTR;
    __nv_bfloat16* svh = skl + 64 * FSTR;
    __nv_bfloat16* svl = svh + 64 * FSTR;

    const int tid = threadIdx.x, lane = tid & 31, w = tid >> 5;
    const int b  = blockIdx.y;
    const int r0 = (gridDim.x - 1 - blockIdx.x) * 128;   // heavy blocks first
    const int wr0 = w * 16;

    // load Q (hi/lo) into smem
    const uint4* qhp = (const uint4*)(g_qh + ((size_t)b * T_ + r0) * H_);
    const uint4* qlp = (const uint4*)(g_ql + ((size_t)b * T_ + r0) * H_);
#pragma unroll
    for (int it = 0; it < 8; it++) {
        int i = tid + it * 256;               // 2048 uint4
        int row = i >> 4, c8 = (i & 15) * 8;
        *(uint4*)&sqh[row * FSTR + c8] = qhp[i];
        *(uint4*)&sql[row * FSTR + c8] = qlp[i];
    }
    __syncthreads();

    const uint32_t sqh_b = smem_u32(sqh), sql_b = smem_u32(sql);
    const uint32_t skh_b = smem_u32(skh), skl_b = smem_u32(skl);
    const uint32_t svh_b = smem_u32(svh), svl_b = smem_u32(svl);

    const uint32_t qa_off = (uint32_t)(wr0 + (lane & 15)) * (FSTR * 2) + (lane >> 4) * 16;
    const uint32_t kb_off = (uint32_t)((lane & 7) + ((lane >> 4) & 1) * 8) * (FSTR * 2)
                          + ((lane >> 3) & 1) * 16;
    const uint32_t vb_off = (uint32_t)((lane & 7) + ((lane >> 3) & 1) * 8) * (FSTR * 2)
                          + ((lane >> 4) & 1) * 16;

    // Qh fragments resident in registers
    uint32_t qfh[8][4];
#pragma unroll
    for (int u = 0; u < 8; u++) ldsm4(qfh[u], sqh_b + qa_off + u * 32);

    float of[16][4];
#pragma unroll
    for (int j = 0; j < 16; j++)
#pragma unroll
        for (int e = 0; e < 4; e++) of[j][e] = 0.f;
    float m_i[2] = {-1e30f, -1e30f}, l_i[2] = {0.f, 0.f};

    const int ntiles = r0 / 64 + 2;
    for (int t = 0; t < ntiles; t++) {
        const int s0 = t * 64;
        __syncthreads();
        {
            const uint4* khp = (const uint4*)(g_kh + ((size_t)b * T_ + s0) * H_);
            const uint4* klp = (const uint4*)(g_kl + ((size_t)b * T_ + s0) * H_);
            const uint4* vhp = (const uint4*)(g_vh + ((size_t)b * T_ + s0) * H_);
            const uint4* vlp = (const uint4*)(g_vl + ((size_t)b * T_ + s0) * H_);
#pragma unroll
            for (int it = 0; it < 4; it++) {
                int i = tid + it * 256;       // 1024 uint4 per array
                int row = i >> 4, c8 = (i & 15) * 8;
                *(uint4*)&skh[row * FSTR + c8] = khp[i];
                *(uint4*)&skl[row * FSTR + c8] = klp[i];
                *(uint4*)&svh[row * FSTR + c8] = vhp[i];
                *(uint4*)&svl[row * FSTR + c8] = vlp[i];
            }
        }
        __syncthreads();

        // ---- S = Q K^T (3-pass) ----
        float sf[8][4];
#pragma unroll
        for (int j = 0; j < 8; j++)
#pragma unroll
            for (int e = 0; e < 4; e++) sf[j][e] = 0.f;

#pragma unroll
        for (int u = 0; u < 8; u++) {
            uint32_t qfl[4];
            ldsm4(qfl, sql_b + qa_off + u * 32);
#pragma unroll
            for (int jp = 0; jp < 4; jp++) {
                uint32_t bh[4], bl[4];
                const uint32_t o = kb_off + (uint32_t)jp * 16 * (FSTR * 2) + u * 32;
                ldsm4(bh, skh_b + o);
                ldsm4(bl, skl_b + o);
                mma16816(sf[2 * jp],     qfh[u], bh[0], bh[1]);
                mma16816(sf[2 * jp],     qfh[u], bl[0], bl[1]);
                mma16816(sf[2 * jp],     qfl,    bh[0], bh[1]);
                mma16816(sf[2 * jp + 1], qfh[u], bh[2], bh[3]);
                mma16816(sf[2 * jp + 1], qfh[u], bl[2], bl[3]);
                mma16816(sf[2 * jp + 1], qfl,    bh[2], bh[3]);
            }
        }

        // ---- causal mask (only near the diagonal) ----
        const int rowg0 = r0 + wr0 + (lane >> 2);
        if (s0 + 63 > rowg0) {
#pragma unroll
            for (int j = 0; j < 8; j++) {
                const int colg = s0 + 8 * j + (lane & 3) * 2;
#pragma unroll
                for (int i = 0; i < 2; i++) {
                    const int rg = rowg0 + 8 * i;
                    if (colg     > rg) sf[j][2 * i]     = -1e30f;
                    if (colg + 1 > rg) sf[j][2 * i + 1] = -1e30f;
                }
            }
        }

        // ---- online softmax (quad shfl reductions) ----
#pragma unroll
        for (int i = 0; i < 2; i++) {
            float mx = sf[0][2 * i];
#pragma unroll
            for (int j = 0; j < 8; j++) {
                mx = fmaxf(mx, sf[j][2 * i]);
                mx = fmaxf(mx, sf[j][2 * i + 1]);
            }
            mx = fmaxf(mx, __shfl_xor_sync(0xffffffffu, mx, 1));
            mx = fmaxf(mx, __shfl_xor_sync(0xffffffffu, mx, 2));
            const float mn  = fmaxf(m_i[i], mx);
            const float fac = __expf(m_i[i] - mn);
            m_i[i] = mn;
            float rs = 0.f;
#pragma unroll
            for (int j = 0; j < 8; j++) {
                float p0 = __expf(sf[j][2 * i]     - mn);
                float p1 = __expf(sf[j][2 * i + 1] - mn);
                sf[j][2 * i] = p0; sf[j][2 * i + 1] = p1;
                rs += p0 + p1;
            }
            rs += __shfl_xor_sync(0xffffffffu, rs, 1);
            rs += __shfl_xor_sync(0xffffffffu, rs, 2);
            l_i[i] = l_i[i] * fac + rs;
#pragma unroll
            for (int j = 0; j < 16; j++) {
                of[j][2 * i] *= fac; of[j][2 * i + 1] *= fac;
            }
        }

        // ---- O += P V (3-pass); P frags packed from S C-frags in-register ----
#pragma unroll
        for (int u = 0; u < 4; u++) {
            uint32_t ph[4], pl[4];
            ph[0] = split_pack(sf[2 * u][0],     sf[2 * u][1],     pl[0]);
            ph[1] = split_pack(sf[2 * u][2],     sf[2 * u][3],     pl[1]);
            ph[2] = split_pack(sf[2 * u + 1][0], sf[2 * u + 1][1], pl[2]);
            ph[3] = split_pack(sf[2 * u + 1][2], sf[2 * u + 1][3], pl[3]);
#pragma unroll
            for (int jp = 0; jp < 8; jp++) {
                uint32_t vh4[4], vl4[4];
                const uint32_t o = vb_off + (uint32_t)u * 16 * (FSTR * 2) + jp * 32;
                ldsm4t(vh4, svh_b + o);
                ldsm4t(vl4, svl_b + o);
                mma16816(of[2 * jp],     ph, vh4[0], vh4[1]);
                mma16816(of[2 * jp],     ph, vl4[0], vl4[1]);
                mma16816(of[2 * jp],     pl, vh4[0], vh4[1]);
                mma16816(of[2 * jp + 1], ph, vh4[2], vh4[3]);
                mma16816(of[2 * jp + 1], ph, vl4[2], vl4[3]);
                mma16816(of[2 * jp + 1], pl, vh4[2], vh4[3]);
            }
        }
    }

    // ---- write O ----
    const float inv0 = 1.0f / l_i[0], inv1 = 1.0f / l_i[1];
#pragma unroll
    for (int j = 0; j < 16; j++)
#pragma unroll
        for (int i = 0; i < 2; i++) {
            const size_t row = (size_t)b * T_ + r0 + wr0 + (lane >> 2) + 8 * i;
            const int col = 8 * j + (lane & 3) * 2;
            const float inv = i ? inv1 : inv0;
            float2 v = make_float2(of[j][2 * i] * inv, of[j][2 * i + 1] * inv);
            *(float2*)&out[row * H_ + col] = v;
        }
}

// ---------------------------------------------------------------------------
extern "C" void kernel_launch(void* const* d_in, const int* in_sizes, int n_in,
                              void* d_out, int out_size)
{
    const float* x  = (const float*)d_in[0];
    const float* Wk = (const float*)d_in[1];
    const float* Wq = (const float*)d_in[2];
    const float* Wv = (const float*)d_in[3];
    float* out = (float*)d_out;

    cudaFuncSetAttribute(qkv_mma_kernel,
                         cudaFuncAttributeMaxDynamicSharedMemorySize, P_SMEM);
    cudaFuncSetAttribute(flash_kernel,
                         cudaFuncAttributeMaxDynamicSharedMemorySize, F_SMEM);

    convert_x_kernel<<<(M_ * (size_t)C_ / 4) / 256, 256>>>(x);
    convert_w_kernel<<<dim3((H_ * C_ / 4) / 256, 3, 1), 256>>>(Wk, Wq, Wv);
    qkv_mma_kernel<<<dim3(M_ / 128, 3, 1), 256, P_SMEM>>>();
    flash_kernel<<<dim3(T_ / 128, B_, 1), 256, F_SMEM>>>(out);
}

// round 4
// speedup vs baseline: 3.7944x; 1.5431x over previous
#include <cuda_runtime.h>
#include <cuda_bf16.h>
#include <cstdint>

#define B_ 8
#define T_ 4096
#define C_ 1024
#define H_ 128
#define M_ (B_ * T_)   // 32768

// ---------------- device scratch (allocation-free rule) ----------------
__device__ __nv_bfloat16 g_xh[(size_t)M_ * C_];
__device__ __nv_bfloat16 g_xl[(size_t)M_ * C_];
__device__ __nv_bfloat16 g_wh[3][(size_t)H_ * C_];
__device__ __nv_bfloat16 g_wl[3][(size_t)H_ * C_];
__device__ __nv_bfloat16 g_qh[(size_t)M_ * H_], g_ql[(size_t)M_ * H_];
__device__ __nv_bfloat16 g_kh[(size_t)M_ * H_], g_kl[(size_t)M_ * H_];
__device__ __nv_bfloat16 g_vh[(size_t)M_ * H_], g_vl[(size_t)M_ * H_];

// ---------------- helpers ----------------
__device__ __forceinline__ uint32_t smem_u32(const void* p) {
    uint32_t a;
    asm("{ .reg .u64 t; cvta.to.shared.u64 t, %1; cvt.u32.u64 %0, t; }"
        : "=r"(a) : "l"(p));
    return a;
}
__device__ __forceinline__ void ldsm4(uint32_t r[4], uint32_t a) {
    asm volatile("ldmatrix.sync.aligned.m8n8.x4.shared.b16 {%0,%1,%2,%3}, [%4];"
        : "=r"(r[0]), "=r"(r[1]), "=r"(r[2]), "=r"(r[3]) : "r"(a));
}
__device__ __forceinline__ void ldsm4t(uint32_t r[4], uint32_t a) {
    asm volatile("ldmatrix.sync.aligned.m8n8.x4.trans.shared.b16 {%0,%1,%2,%3}, [%4];"
        : "=r"(r[0]), "=r"(r[1]), "=r"(r[2]), "=r"(r[3]) : "r"(a));
}
__device__ __forceinline__ void mma16816(float c[4], const uint32_t a[4],
                                         uint32_t b0, uint32_t b1) {
    asm volatile(
        "mma.sync.aligned.m16n8k16.row.col.f32.bf16.bf16.f32 "
        "{%0,%1,%2,%3}, {%4,%5,%6,%7}, {%8,%9}, {%0,%1,%2,%3};"
        : "+f"(c[0]), "+f"(c[1]), "+f"(c[2]), "+f"(c[3])
        : "r"(a[0]), "r"(a[1]), "r"(a[2]), "r"(a[3]), "r"(b0), "r"(b1));
}
__device__ __forceinline__ uint32_t split_pack(float v0, float v1, uint32_t& lo) {
    __nv_bfloat16 h0 = __float2bfloat16(v0), h1 = __float2bfloat16(v1);
    __nv_bfloat16 l0 = __float2bfloat16(v0 - __bfloat162float(h0));
    __nv_bfloat16 l1 = __float2bfloat16(v1 - __bfloat162float(h1));
    __nv_bfloat162 L(l0, l1), Hh(h0, h1);
    lo = *reinterpret_cast<uint32_t*>(&L);
    return *reinterpret_cast<uint32_t*>(&Hh);
}

#define CP16(dst, src) \
    asm volatile("cp.async.cg.shared.global [%0], [%1], 16;" \
                 :: "r"(dst), "l"(src) : "memory")
#define CP_COMMIT() asm volatile("cp.async.commit_group;" ::: "memory")
#define CP_WAIT1()  asm volatile("cp.async.wait_group 1;" ::: "memory")

// ---------------- fp32 -> bf16 hi/lo conversions ----------------
__global__ __launch_bounds__(256) void convert_x_kernel(const float* __restrict__ x)
{
    size_t i = (size_t)blockIdx.x * 256 + threadIdx.x;
    float4 v = ((const float4*)x)[i];
    uint32_t l01, l23;
    uint32_t h01 = split_pack(v.x, v.y, l01);
    uint32_t h23 = split_pack(v.z, v.w, l23);
    ((uint32_t*)g_xh)[2 * i + 0] = h01; ((uint32_t*)g_xh)[2 * i + 1] = h23;
    ((uint32_t*)g_xl)[2 * i + 0] = l01; ((uint32_t*)g_xl)[2 * i + 1] = l23;
}
__global__ __launch_bounds__(256) void convert_w_kernel(
    const float* __restrict__ Wk, const float* __restrict__ Wq,
    const float* __restrict__ Wv)
{
    const int sel = blockIdx.y;
    const float* W = (sel == 0) ? Wq : (sel == 1) ? Wk : Wv;
    size_t i = (size_t)blockIdx.x * 256 + threadIdx.x;
    float4 v = ((const float4*)W)[i];
    uint32_t l01, l23;
    uint32_t h01 = split_pack(v.x, v.y, l01);
    uint32_t h23 = split_pack(v.z, v.w, l23);
    ((uint32_t*)g_wh[sel])[2 * i + 0] = h01; ((uint32_t*)g_wh[sel])[2 * i + 1] = h23;
    ((uint32_t*)g_wl[sel])[2 * i + 0] = l01; ((uint32_t*)g_wl[sel])[2 * i + 1] = l23;
}

// ---------------- QKV projection: mma.sync bf16x3, cp.async double-buffer ----
#define PSTR   72
#define PARR   (128 * PSTR)            // elems per array
#define PSTAGE (4 * PARR)              // elems per stage (xh,xl,wh,wl)
#define P_SMEM (2 * PSTAGE * 2)        // bytes = 147456

__global__ __launch_bounds__(256) void qkv_mma_kernel()
{
    extern __shared__ __nv_bfloat16 ps[];

    const int tid = threadIdx.x, lane = tid & 31, w = tid >> 5;
    const int sel = blockIdx.y;
    const int m0  = blockIdx.x * 128;
    const int wr0 = w * 16;

    const __nv_bfloat16* xh = g_xh + (size_t)m0 * C_;
    const __nv_bfloat16* xl = g_xl + (size_t)m0 * C_;
    const __nv_bfloat16* wh = g_wh[sel];
    const __nv_bfloat16* wl = g_wl[sel];

    const uint32_t base = smem_u32(ps);

    // per-thread cp.async smem offsets (bytes, relative to array base)
    uint32_t cpo[4];
    int      go[4];
#pragma unroll
    for (int it = 0; it < 4; it++) {
        int i   = tid + it * 256;          // 1024 uint4 per array
        int row = i >> 3, c8 = (i & 7) * 8;
        cpo[it] = (uint32_t)(row * PSTR + c8) * 2;
        go[it]  = row * C_ + c8;           // add k0 at use
    }

    auto issue = [&](int kc, int s) {
        const int k0 = kc * 64;
        const uint32_t sb = base + (uint32_t)(s * PSTAGE) * 2;
#pragma unroll
        for (int it = 0; it < 4; it++) {
            const size_t g = (size_t)go[it] + k0;
            CP16(sb + 0 * PARR * 2 + cpo[it], (const char*)(xh + g));
            CP16(sb + 1 * PARR * 2 + cpo[it], (const char*)(xl + g));
            CP16(sb + 2 * PARR * 2 + cpo[it], (const char*)(wh + g));
            CP16(sb + 3 * PARR * 2 + cpo[it], (const char*)(wl + g));
        }
    };

    float of[16][4];
#pragma unroll
    for (int j = 0; j < 16; j++)
#pragma unroll
        for (int e = 0; e < 4; e++) of[j][e] = 0.f;

    const uint32_t a_off = (uint32_t)(wr0 + (lane & 15)) * (PSTR * 2) + (lane >> 4) * 16;
    const uint32_t b_off = (uint32_t)((lane & 7) + ((lane >> 4) & 1) * 8) * (PSTR * 2)
                         + ((lane >> 3) & 1) * 16;

    issue(0, 0);
    CP_COMMIT();

    const int NC = C_ / 64;   // 16
    for (int kc = 0; kc < NC; kc++) {
        const int p = kc & 1;
        if (kc + 1 < NC) issue(kc + 1, 1 - p);
        CP_COMMIT();
        CP_WAIT1();
        __syncthreads();

        const uint32_t sb    = base + (uint32_t)(p * PSTAGE) * 2;
        const uint32_t sxh_b = sb,                sxl_b = sb + 1 * PARR * 2;
        const uint32_t swh_b = sb + 2 * PARR * 2, swl_b = sb + 3 * PARR * 2;

#pragma unroll
        for (int u = 0; u < 4; u++) {
            uint32_t axh[4], axl[4];
            ldsm4(axh, sxh_b + a_off + u * 32);
            ldsm4(axl, sxl_b + a_off + u * 32);
#pragma unroll
            for (int jp = 0; jp < 8; jp++) {
                uint32_t bh[4], bl[4];
                const uint32_t o = b_off + (uint32_t)jp * 16 * (PSTR * 2) + u * 32;
                ldsm4(bh, swh_b + o);
                ldsm4(bl, swl_b + o);
                mma16816(of[2 * jp],     axh, bh[0], bh[1]);
                mma16816(of[2 * jp],     axh, bl[0], bl[1]);
                mma16816(of[2 * jp],     axl, bh[0], bh[1]);
                mma16816(of[2 * jp + 1], axh, bh[2], bh[3]);
                mma16816(of[2 * jp + 1], axh, bl[2], bl[3]);
                mma16816(of[2 * jp + 1], axl, bh[2], bh[3]);
            }
        }
        __syncthreads();
    }

    const float scl = (sel == 0) ? 0.08838834764831845f : 1.0f;   // q: 1/sqrt(128)
    __nv_bfloat16* oh = (sel == 0) ? g_qh : (sel == 1) ? g_kh : g_vh;
    __nv_bfloat16* ol = (sel == 0) ? g_ql : (sel == 1) ? g_kl : g_vl;
#pragma unroll
    for (int j = 0; j < 16; j++)
#pragma unroll
        for (int i = 0; i < 2; i++) {
            const size_t row = (size_t)(m0 + wr0 + (lane >> 2) + 8 * i);
            const int col = 8 * j + (lane & 3) * 2;
            uint32_t lo;
            uint32_t hi = split_pack(of[j][2 * i] * scl, of[j][2 * i + 1] * scl, lo);
            *(uint32_t*)&oh[row * H_ + col] = hi;
            *(uint32_t*)&ol[row * H_ + col] = lo;
        }
}

// ---------------- flash attention: mma.sync bf16x3, cp.async KV pipeline ----
#define FSTR   136
#define FQ     (128 * FSTR)
#define FKV    (64 * FSTR)
#define FSTAGE (4 * FKV)
#define F_SMEM ((2 * FQ + 2 * FSTAGE) * 2)   // 208896 B

__global__ __launch_bounds__(256) void flash_kernel(float* __restrict__ out)
{
    extern __shared__ __nv_bfloat16 fs[];
    __nv_bfloat16* sqh = fs;
    __nv_bfloat16* sql = sqh + FQ;

    const int tid = threadIdx.x, lane = tid & 31, w = tid >> 5;
    const int b   = blockIdx.x;
    const int r0  = (gridDim.y - 1 - blockIdx.y) * 128;   // heavy rows first
    const int wr0 = w * 16;

    const uint32_t base   = smem_u32(fs);
    const uint32_t kvbase = base + (uint32_t)(2 * FQ) * 2;

    // per-thread cp.async offsets for a KV stage
    uint32_t cpo[4];
    int      go[4];
#pragma unroll
    for (int it = 0; it < 4; it++) {
        int i   = tid + it * 256;            // 1024 uint4 per array
        int row = i >> 4, c8 = (i & 15) * 8;
        cpo[it] = (uint32_t)(row * FSTR + c8) * 2;
        go[it]  = row * H_ + c8;
    }

    const size_t bbase = (size_t)b * T_ * H_;
    auto issue = [&](int t, int s) {
        const size_t off = bbase + (size_t)t * 64 * H_;
        const __nv_bfloat16* kh = g_kh + off;
        const __nv_bfloat16* kl = g_kl + off;
        const __nv_bfloat16* vh = g_vh + off;
        const __nv_bfloat16* vl = g_vl + off;
        const uint32_t sb = kvbase + (uint32_t)(s * FSTAGE) * 2;
#pragma unroll
        for (int it = 0; it < 4; it++) {
            CP16(sb + 0 * FKV * 2 + cpo[it], (const char*)(kh + go[it]));
            CP16(sb + 1 * FKV * 2 + cpo[it], (const char*)(kl + go[it]));
            CP16(sb + 2 * FKV * 2 + cpo[it], (const char*)(vh + go[it]));
            CP16(sb + 3 * FKV * 2 + cpo[it], (const char*)(vl + go[it]));
        }
    };

    // kick off tile 0, then load Q while it flies
    issue(0, 0);
    CP_COMMIT();

    const uint4* qhp = (const uint4*)(g_qh + bbase + (size_t)r0 * H_);
    const uint4* qlp = (const uint4*)(g_ql + bbase + (size_t)r0 * H_);
#pragma unroll
    for (int it = 0; it < 8; it++) {
        int i = tid + it * 256;               // 2048 uint4
        int row = i >> 4, c8 = (i & 15) * 8;
        *(uint4*)&sqh[row * FSTR + c8] = qhp[i];
        *(uint4*)&sql[row * FSTR + c8] = qlp[i];
    }
    __syncthreads();

    const uint32_t sqh_b = base;
    const uint32_t sql_b = base + (uint32_t)FQ * 2;

    const uint32_t qa_off = (uint32_t)(wr0 + (lane & 15)) * (FSTR * 2) + (lane >> 4) * 16;
    const uint32_t kb_off = (uint32_t)((lane & 7) + ((lane >> 4) & 1) * 8) * (FSTR * 2)
                          + ((lane >> 3) & 1) * 16;
    const uint32_t vb_off = (uint32_t)((lane & 7) + ((lane >> 3) & 1) * 8) * (FSTR * 2)
                          + ((lane >> 4) & 1) * 16;

    uint32_t qfh[8][4];
#pragma unroll
    for (int u = 0; u < 8; u++) ldsm4(qfh[u], sqh_b + qa_off + u * 32);

    float of[16][4];
#pragma unroll
    for (int j = 0; j < 16; j++)
#pragma unroll
        for (int e = 0; e < 4; e++) of[j][e] = 0.f;
    float m_i[2] = {-1e30f, -1e30f}, l_i[2] = {0.f, 0.f};

    const int ntiles = r0 / 64 + 2;
    for (int t = 0; t < ntiles; t++) {
        const int p  = t & 1;
        const int s0 = t * 64;
        if (t + 1 < ntiles) issue(t + 1, 1 - p);
        CP_COMMIT();
        CP_WAIT1();
        __syncthreads();

        const uint32_t sb    = kvbase + (uint32_t)(p * FSTAGE) * 2;
        const uint32_t skh_b = sb,                skl_b = sb + 1 * FKV * 2;
        const uint32_t svh_b = sb + 2 * FKV * 2,  svl_b = sb + 3 * FKV * 2;

        // ---- S = Q K^T (3-pass) ----
        float sf[8][4];
#pragma unroll
        for (int j = 0; j < 8; j++)
#pragma unroll
            for (int e = 0; e < 4; e++) sf[j][e] = 0.f;

#pragma unroll
        for (int u = 0; u < 8; u++) {
            uint32_t qfl[4];
            ldsm4(qfl, sql_b + qa_off + u * 32);
#pragma unroll
            for (int jp = 0; jp < 4; jp++) {
                uint32_t bh[4], bl[4];
                const uint32_t o = kb_off + (uint32_t)jp * 16 * (FSTR * 2) + u * 32;
                ldsm4(bh, skh_b + o);
                ldsm4(bl, skl_b + o);
                mma16816(sf[2 * jp],     qfh[u], bh[0], bh[1]);
                mma16816(sf[2 * jp],     qfh[u], bl[0], bl[1]);
                mma16816(sf[2 * jp],     qfl,    bh[0], bh[1]);
                mma16816(sf[2 * jp + 1], qfh[u], bh[2], bh[3]);
                mma16816(sf[2 * jp + 1], qfh[u], bl[2], bl[3]);
                mma16816(sf[2 * jp + 1], qfl,    bh[2], bh[3]);
            }
        }

        // ---- causal mask ----
        const int rowg0 = r0 + wr0 + (lane >> 2);
        if (s0 + 63 > rowg0) {
#pragma unroll
            for (int j = 0; j < 8; j++) {
                const int colg = s0 + 8 * j + (lane & 3) * 2;
#pragma unroll
                for (int i = 0; i < 2; i++) {
                    const int rg = rowg0 + 8 * i;
                    if (colg     > rg) sf[j][2 * i]     = -1e30f;
                    if (colg + 1 > rg) sf[j][2 * i + 1] = -1e30f;
                }
            }
        }

        // ---- online softmax ----
#pragma unroll
        for (int i = 0; i < 2; i++) {
            float mx = sf[0][2 * i];
#pragma unroll
            for (int j = 0; j < 8; j++) {
                mx = fmaxf(mx, sf[j][2 * i]);
                mx = fmaxf(mx, sf[j][2 * i + 1]);
            }
            mx = fmaxf(mx, __shfl_xor_sync(0xffffffffu, mx, 1));
            mx = fmaxf(mx, __shfl_xor_sync(0xffffffffu, mx, 2));
            const float mn  = fmaxf(m_i[i], mx);
            const float fac = __expf(m_i[i] - mn);
            m_i[i] = mn;
            float rs = 0.f;
#pragma unroll
            for (int j = 0; j < 8; j++) {
                float p0 = __expf(sf[j][2 * i]     - mn);
                float p1 = __expf(sf[j][2 * i + 1] - mn);
                sf[j][2 * i] = p0; sf[j][2 * i + 1] = p1;
                rs += p0 + p1;
            }
            rs += __shfl_xor_sync(0xffffffffu, rs, 1);
            rs += __shfl_xor_sync(0xffffffffu, rs, 2);
            l_i[i] = l_i[i] * fac + rs;
#pragma unroll
            for (int j = 0; j < 16; j++) {
                of[j][2 * i] *= fac; of[j][2 * i + 1] *= fac;
            }
        }

        // ---- O += P V (3-pass) ----
#pragma unroll
        for (int u = 0; u < 4; u++) {
            uint32_t ph[4], pl[4];
            ph[0] = split_pack(sf[2 * u][0],     sf[2 * u][1],     pl[0]);
            ph[1] = split_pack(sf[2 * u][2],     sf[2 * u][3],     pl[1]);
            ph[2] = split_pack(sf[2 * u + 1][0], sf[2 * u + 1][1], pl[2]);
            ph[3] = split_pack(sf[2 * u + 1][2], sf[2 * u + 1][3], pl[3]);
#pragma unroll
            for (int jp = 0; jp < 8; jp++) {
                uint32_t vh4[4], vl4[4];
                const uint32_t o = vb_off + (uint32_t)u * 16 * (FSTR * 2) + jp * 32;
                ldsm4t(vh4, svh_b + o);
                ldsm4t(vl4, svl_b + o);
                mma16816(of[2 * jp],     ph, vh4[0], vh4[1]);
                mma16816(of[2 * jp],     ph, vl4[0], vl4[1]);
                mma16816(of[2 * jp],     pl, vh4[0], vh4[1]);
                mma16816(of[2 * jp + 1], ph, vh4[2], vh4[3]);
                mma16816(of[2 * jp + 1], ph, vl4[2], vl4[3]);
                mma16816(of[2 * jp + 1], pl, vh4[2], vh4[3]);
            }
        }
        __syncthreads();
    }

    // ---- write O ----
    const float inv0 = 1.0f / l_i[0], inv1 = 1.0f / l_i[1];
#pragma unroll
    for (int j = 0; j < 16; j++)
#pragma unroll
        for (int i = 0; i < 2; i++) {
            const size_t row = (size_t)b * T_ + r0 + wr0 + (lane >> 2) + 8 * i;
            const int col = 8 * j + (lane & 3) * 2;
            const float inv = i ? inv1 : inv0;
            float2 v = make_float2(of[j][2 * i] * inv, of[j][2 * i + 1] * inv);
            *(float2*)&out[row * H_ + col] = v;
        }
}

// ---------------------------------------------------------------------------
extern "C" void kernel_launch(void* const* d_in, const int* in_sizes, int n_in,
                              void* d_out, int out_size)
{
    const float* x  = (const float*)d_in[0];
    const float* Wk = (const float*)d_in[1];
    const float* Wq = (const float*)d_in[2];
    const float* Wv = (const float*)d_in[3];
    float* out = (float*)d_out;

    cudaFuncSetAttribute(qkv_mma_kernel,
                         cudaFuncAttributeMaxDynamicSharedMemorySize, P_SMEM);
    cudaFuncSetAttribute(flash_kernel,
                         cudaFuncAttributeMaxDynamicSharedMemorySize, F_SMEM);

    convert_x_kernel<<<(M_ * (size_t)C_ / 4) / 256, 256>>>(x);
    convert_w_kernel<<<dim3((H_ * C_ / 4) / 256, 3, 1), 256>>>(Wk, Wq, Wv);
    qkv_mma_kernel<<<dim3(M_ / 128, 3, 1), 256, P_SMEM>>>();
    flash_kernel<<<dim3(B_, T_ / 128, 1), 256, F_SMEM>>>(out);
}

// round 7
// speedup vs baseline: 8.4543x; 2.2281x over previous
#include <cuda_runtime.h>
#include <cuda_fp16.h>
#include <cstdint>

#define B_ 8
#define T_ 4096
#define C_ 1024
#define H_ 128
#define M_ (B_ * T_)   // 32768

// ---------------- device scratch (allocation-free rule) ----------------
__device__ __half g_x16[(size_t)M_ * C_];
__device__ __half g_w16[3][(size_t)H_ * C_];
__device__ __half g_q16[(size_t)M_ * H_];
__device__ __half g_k16[(size_t)M_ * H_];
__device__ __half g_v16[(size_t)M_ * H_];

// ---------------- helpers ----------------
__device__ __forceinline__ uint32_t smem_u32(const void* p) {
    uint32_t a;
    asm("{ .reg .u64 t; cvta.to.shared.u64 t, %1; cvt.u32.u64 %0, t; }"
        : "=r"(a) : "l"(p));
    return a;
}
__device__ __forceinline__ void ldsm4(uint32_t r[4], uint32_t a) {
    asm volatile("ldmatrix.sync.aligned.m8n8.x4.shared.b16 {%0,%1,%2,%3}, [%4];"
        : "=r"(r[0]), "=r"(r[1]), "=r"(r[2]), "=r"(r[3]) : "r"(a));
}
__device__ __forceinline__ void ldsm4t(uint32_t r[4], uint32_t a) {
    asm volatile("ldmatrix.sync.aligned.m8n8.x4.trans.shared.b16 {%0,%1,%2,%3}, [%4];"
        : "=r"(r[0]), "=r"(r[1]), "=r"(r[2]), "=r"(r[3]) : "r"(a));
}
__device__ __forceinline__ void mma16816(float c[4], const uint32_t a[4],
                                         uint32_t b0, uint32_t b1) {
    asm volatile(
        "mma.sync.aligned.m16n8k16.row.col.f32.f16.f16.f32 "
        "{%0,%1,%2,%3}, {%4,%5,%6,%7}, {%8,%9}, {%0,%1,%2,%3};"
        : "+f"(c[0]), "+f"(c[1]), "+f"(c[2]), "+f"(c[3])
        : "r"(a[0]), "r"(a[1]), "r"(a[2]), "r"(a[3]), "r"(b0), "r"(b1));
}
__device__ __forceinline__ uint32_t pack_h2(float a, float b) {
    __half2 h = __floats2half2_rn(a, b);
    return *reinterpret_cast<uint32_t*>(&h);
}

#define CP16(dst, src) \
    asm volatile("cp.async.cg.shared.global [%0], [%1], 16;" \
                 :: "r"(dst), "l"(src) : "memory")
#define CP_COMMIT() asm volatile("cp.async.commit_group;" ::: "memory")
#define CP_WAIT1()  asm volatile("cp.async.wait_group 1;" ::: "memory")
#define CP_WAIT2()  asm volatile("cp.async.wait_group 2;" ::: "memory")

// ---------------- fp32 -> fp16 conversions ----------------
__global__ __launch_bounds__(256) void convert_x_kernel(const float* __restrict__ x)
{
    size_t i = (size_t)blockIdx.x * 256 + threadIdx.x;
    float4 v = ((const float4*)x)[i];
    uint2 o;
    o.x = pack_h2(v.x, v.y);
    o.y = pack_h2(v.z, v.w);
    ((uint2*)g_x16)[i] = o;
}
__global__ __launch_bounds__(256) void convert_w_kernel(
    const float* __restrict__ Wk, const float* __restrict__ Wq,
    const float* __restrict__ Wv)
{
    const int sel = blockIdx.y;
    const float* W = (sel == 0) ? Wq : (sel == 1) ? Wk : Wv;
    size_t i = (size_t)blockIdx.x * 256 + threadIdx.x;
    float4 v = ((const float4*)W)[i];
    uint2 o;
    o.x = pack_h2(v.x, v.y);
    o.y = pack_h2(v.z, v.w);
    ((uint2*)g_w16[sel])[i] = o;
}

// ---------------- QKV projection: mma.sync fp16, cp.async double-buffer ----
#define PSTR   72
#define PARR   (128 * PSTR)            // elems per array
#define PSTAGE (2 * PARR)              // elems per stage (x, w)
#define P_SMEM (2 * PSTAGE * 2)        // bytes = 73728

__global__ __launch_bounds__(256) void qkv_mma_kernel()
{
    extern __shared__ __half ps[];

    const int tid = threadIdx.x, lane = tid & 31, w = tid >> 5;
    const int sel = blockIdx.y;
    const int m0  = blockIdx.x * 128;
    const int wr0 = w * 16;

    const __half* xp = g_x16 + (size_t)m0 * C_;
    const __half* wp = g_w16[sel];

    const uint32_t base = smem_u32(ps);

    uint32_t cpo[4];
    int      go[4];
#pragma unroll
    for (int it = 0; it < 4; it++) {
        int i   = tid + it * 256;          // 1024 uint4 per array
        int row = i >> 3, c8 = (i & 7) * 8;
        cpo[it] = (uint32_t)(row * PSTR + c8) * 2;
        go[it]  = row * C_ + c8;
    }

    auto issue = [&](int kc, int s) {
        const int k0 = kc * 64;
        const uint32_t sb = base + (uint32_t)(s * PSTAGE) * 2;
#pragma unroll
        for (int it = 0; it < 4; it++) {
            const size_t g = (size_t)go[it] + k0;
            CP16(sb + cpo[it],                (const char*)(xp + g));
            CP16(sb + PARR * 2 + cpo[it],     (const char*)(wp + g));
        }
    };

    float of[16][4];
#pragma unroll
    for (int j = 0; j < 16; j++)
#pragma unroll
        for (int e = 0; e < 4; e++) of[j][e] = 0.f;

    const uint32_t a_off = (uint32_t)(wr0 + (lane & 15)) * (PSTR * 2) + (lane >> 4) * 16;
    const uint32_t b_off = (uint32_t)((lane & 7) + ((lane >> 4) & 1) * 8) * (PSTR * 2)
                         + ((lane >> 3) & 1) * 16;

    issue(0, 0);
    CP_COMMIT();

    const int NC = C_ / 64;   // 16
    for (int kc = 0; kc < NC; kc++) {
        const int p = kc & 1;
        if (kc + 1 < NC) issue(kc + 1, 1 - p);
        CP_COMMIT();
        CP_WAIT1();
        __syncthreads();

        const uint32_t sb   = base + (uint32_t)(p * PSTAGE) * 2;
        const uint32_t sx_b = sb;
        const uint32_t sw_b = sb + PARR * 2;

#pragma unroll
        for (int u = 0; u < 4; u++) {
            uint32_t ax[4];
            ldsm4(ax, sx_b + a_off + u * 32);
#pragma unroll
            for (int jp = 0; jp < 8; jp++) {
                uint32_t bh[4];
                ldsm4(bh, sw_b + b_off + (uint32_t)jp * 16 * (PSTR * 2) + u * 32);
                mma16816(of[2 * jp],     ax, bh[0], bh[1]);
                mma16816(of[2 * jp + 1], ax, bh[2], bh[3]);
            }
        }
        __syncthreads();
    }

    const float scl = (sel == 0) ? 0.08838834764831845f : 1.0f;   // q: 1/sqrt(128)
    __half* op = (sel == 0) ? g_q16 : (sel == 1) ? g_k16 : g_v16;
#pragma unroll
    for (int j = 0; j < 16; j++)
#pragma unroll
        for (int i = 0; i < 2; i++) {
            const size_t row = (size_t)(m0 + wr0 + (lane >> 2) + 8 * i);
            const int col = 8 * j + (lane & 3) * 2;
            *(uint32_t*)&op[row * H_ + col] =
                pack_h2(of[j][2 * i] * scl, of[j][2 * i + 1] * scl);
        }
}

// ---------------- flash attention: mma.sync fp16, 3-stage cp.async KV ring ----
#define FSTR   136
#define FQ     (128 * FSTR)
#define FKV    (64 * FSTR)
#define FSTAGE (2 * FKV)                      // K + V
#define F_SMEM ((FQ + 3 * FSTAGE) * 2)        // 139264 B

__global__ __launch_bounds__(256) void flash_kernel(float* __restrict__ out)
{
    extern __shared__ __half fs[];
    __half* sq = fs;

    const int tid = threadIdx.x, lane = tid & 31, w = tid >> 5;
    const int b   = blockIdx.x;
    const int r0  = (gridDim.y - 1 - blockIdx.y) * 128;   // heavy rows first
    const int wr0 = w * 16;

    const uint32_t base   = smem_u32(fs);
    const uint32_t kvbase = base + (uint32_t)FQ * 2;

    uint32_t cpo[4];
    int      go[4];
#pragma unroll
    for (int it = 0; it < 4; it++) {
        int i   = tid + it * 256;            // 1024 uint4 per array
        int row = i >> 4, c8 = (i & 15) * 8;
        cpo[it] = (uint32_t)(row * FSTR + c8) * 2;
        go[it]  = row * H_ + c8;
    }

    const size_t bbase = (size_t)b * T_ * H_;
    auto issue = [&](int t, int s) {
        const size_t off = bbase + (size_t)t * 64 * H_;
        const __half* kp = g_k16 + off;
        const __half* vp = g_v16 + off;
        const uint32_t sb = kvbase + (uint32_t)(s * FSTAGE) * 2;
#pragma unroll
        for (int it = 0; it < 4; it++) {
            CP16(sb + cpo[it],             (const char*)(kp + go[it]));
            CP16(sb + FKV * 2 + cpo[it],   (const char*)(vp + go[it]));
        }
    };

    const int ntiles = r0 / 64 + 2;

    // prologue: 2 tiles in flight, then load Q
    issue(0, 0); CP_COMMIT();
    issue(1, 1); CP_COMMIT();

    // Q tile: 128 rows x 128 halfs = 2048 uint4  (FIX: it < 8, was it < 4)
    const uint4* qp = (const uint4*)(g_q16 + bbase + (size_t)r0 * H_);
#pragma unroll
    for (int it = 0; it < 8; it++) {
        int i = tid + it * 256;               // 2048 uint4
        int row = i >> 4, c8 = (i & 15) * 8;
        *(uint4*)&sq[row * FSTR + c8] = qp[i];
    }
    __syncthreads();

    const uint32_t qa_off = (uint32_t)(wr0 + (lane & 15)) * (FSTR * 2) + (lane >> 4) * 16;
    const uint32_t kb_off = (uint32_t)((lane & 7) + ((lane >> 4) & 1) * 8) * (FSTR * 2)
                          + ((lane >> 3) & 1) * 16;
    const uint32_t vb_off = (uint32_t)((lane & 7) + ((lane >> 3) & 1) * 8) * (FSTR * 2)
                          + ((lane >> 4) & 1) * 16;

    uint32_t qf[8][4];
#pragma unroll
    for (int u = 0; u < 8; u++) ldsm4(qf[u], base + qa_off + u * 32);

    float of[16][4];
#pragma unroll
    for (int j = 0; j < 16; j++)
#pragma unroll
        for (int e = 0; e < 4; e++) of[j][e] = 0.f;
    float m_i[2] = {-1e30f, -1e30f}, l_i[2] = {0.f, 0.f};

    for (int t = 0; t < ntiles; t++) {
        const int s0 = t * 64;
        if (t + 2 < ntiles) { issue(t + 2, (t + 2) % 3); }
        CP_COMMIT();
        CP_WAIT2();
        __syncthreads();

        const uint32_t sb   = kvbase + (uint32_t)((t % 3) * FSTAGE) * 2;
        const uint32_t sk_b = sb;
        const uint32_t sv_b = sb + FKV * 2;

        // ---- S = Q K^T ----
        float sf[8][4];
#pragma unroll
        for (int j = 0; j < 8; j++)
#pragma unroll
            for (int e = 0; e < 4; e++) sf[j][e] = 0.f;

#pragma unroll
        for (int u = 0; u < 8; u++) {
#pragma unroll
            for (int jp = 0; jp < 4; jp++) {
                uint32_t bh[4];
                ldsm4(bh, sk_b + kb_off + (uint32_t)jp * 16 * (FSTR * 2) + u * 32);
                mma16816(sf[2 * jp],     qf[u], bh[0], bh[1]);
                mma16816(sf[2 * jp + 1], qf[u], bh[2], bh[3]);
            }
        }

        // ---- causal mask ----
        const int rowg0 = r0 + wr0 + (lane >> 2);
        if (s0 + 63 > rowg0) {
#pragma unroll
            for (int j = 0; j < 8; j++) {
                const int colg = s0 + 8 * j + (lane & 3) * 2;
#pragma unroll
                for (int i = 0; i < 2; i++) {
                    const int rg = rowg0 + 8 * i;
                    if (colg     > rg) sf[j][2 * i]     = -1e30f;
                    if (colg + 1 > rg) sf[j][2 * i + 1] = -1e30f;
                }
            }
        }

        // ---- online softmax ----
#pragma unroll
        for (int i = 0; i < 2; i++) {
            float mx = sf[0][2 * i];
#pragma unroll
            for (int j = 0; j < 8; j++) {
                mx = fmaxf(mx, sf[j][2 * i]);
                mx = fmaxf(mx, sf[j][2 * i + 1]);
            }
            mx = fmaxf(mx, __shfl_xor_sync(0xffffffffu, mx, 1));
            mx = fmaxf(mx, __shfl_xor_sync(0xffffffffu, mx, 2));
            const float mn  = fmaxf(m_i[i], mx);
            const float fac = __expf(m_i[i] - mn);
            m_i[i] = mn;
            float rs = 0.f;
#pragma unroll
            for (int j = 0; j < 8; j++) {
                float p0 = __expf(sf[j][2 * i]     - mn);
                float p1 = __expf(sf[j][2 * i + 1] - mn);
                sf[j][2 * i] = p0; sf[j][2 * i + 1] = p1;
                rs += p0 + p1;
            }
            rs += __shfl_xor_sync(0xffffffffu, rs, 1);
            rs += __shfl_xor_sync(0xffffffffu, rs, 2);
            l_i[i] = l_i[i] * fac + rs;
#pragma unroll
            for (int j = 0; j < 16; j++) {
                of[j][2 * i] *= fac; of[j][2 * i + 1] *= fac;
            }
        }

        // ---- O += P V ----
#pragma unroll
        for (int u = 0; u < 4; u++) {
            uint32_t ph[4];
            ph[0] = pack_h2(sf[2 * u][0],     sf[2 * u][1]);
            ph[1] = pack_h2(sf[2 * u][2],     sf[2 * u][3]);
            ph[2] = pack_h2(sf[2 * u + 1][0], sf[2 * u + 1][1]);
            ph[3] = pack_h2(sf[2 * u + 1][2], sf[2 * u + 1][3]);
#pragma unroll
            for (int jp = 0; jp < 8; jp++) {
                uint32_t vh[4];
                ldsm4t(vh, sv_b + vb_off + (uint32_t)u * 16 * (FSTR * 2) + jp * 32);
                mma16816(of[2 * jp],     ph, vh[0], vh[1]);
                mma16816(of[2 * jp + 1], ph, vh[2], vh[3]);
            }
        }
        __syncthreads();
    }

    // ---- write O ----
    const float inv0 = 1.0f / l_i[0], inv1 = 1.0f / l_i[1];
#pragma unroll
    for (int j = 0; j < 16; j++)
#pragma unroll
        for (int i = 0; i < 2; i++) {
            const size_t row = (size_t)b * T_ + r0 + wr0 + (lane >> 2) + 8 * i;
            const int col = 8 * j + (lane & 3) * 2;
            const float inv = i ? inv1 : inv0;
            float2 v = make_float2(of[j][2 * i] * inv, of[j][2 * i + 1] * inv);
            *(float2*)&out[row * H_ + col] = v;
        }
}

// ---------------------------------------------------------------------------
extern "C" void kernel_launch(void* const* d_in, const int* in_sizes, int n_in,
                              void* d_out, int out_size)
{
    const float* x  = (const float*)d_in[0];
    const float* Wk = (const float*)d_in[1];
    const float* Wq = (const float*)d_in[2];
    const float* Wv = (const float*)d_in[3];
    float* out = (float*)d_out;

    cudaFuncSetAttribute(qkv_mma_kernel,
                         cudaFuncAttributeMaxDynamicSharedMemorySize, P_SMEM);
    cudaFuncSetAttribute(flash_kernel,
                         cudaFuncAttributeMaxDynamicSharedMemorySize, F_SMEM);

    convert_x_kernel<<<(M_ * (size_t)C_ / 4) / 256, 256>>>(x);
    convert_w_kernel<<<dim3((H_ * C_ / 4) / 256, 3, 1), 256>>>(Wk, Wq, Wv);
    qkv_mma_kernel<<<dim3(M_ / 128, 3, 1), 256, P_SMEM>>>();
    flash_kernel<<<dim3(B_, T_ / 128, 1), 256, F_SMEM>>>(out);
}

// round 8
// speedup vs baseline: 9.0593x; 1.0716x over previous
#include <cuda_runtime.h>
#include <cuda_fp16.h>
#include <cstdint>

#define B_ 8
#define T_ 4096
#define C_ 1024
#define H_ 128
#define M_ (B_ * T_)   // 32768

// ---------------- device scratch (allocation-free rule) ----------------
__device__ __half g_x16[(size_t)M_ * C_];
__device__ __half g_w16[3][(size_t)H_ * C_];
__device__ __half g_q16[(size_t)M_ * H_];
__device__ __half g_k16[(size_t)M_ * H_];
__device__ __half g_v16[(size_t)M_ * H_];

// ---------------- helpers ----------------
__device__ __forceinline__ uint32_t smem_u32(const void* p) {
    uint32_t a;
    asm("{ .reg .u64 t; cvta.to.shared.u64 t, %1; cvt.u32.u64 %0, t; }"
        : "=r"(a) : "l"(p));
    return a;
}
__device__ __forceinline__ void ldsm4(uint32_t r[4], uint32_t a) {
    asm volatile("ldmatrix.sync.aligned.m8n8.x4.shared.b16 {%0,%1,%2,%3}, [%4];"
        : "=r"(r[0]), "=r"(r[1]), "=r"(r[2]), "=r"(r[3]) : "r"(a));
}
__device__ __forceinline__ void ldsm4t(uint32_t r[4], uint32_t a) {
    asm volatile("ldmatrix.sync.aligned.m8n8.x4.trans.shared.b16 {%0,%1,%2,%3}, [%4];"
        : "=r"(r[0]), "=r"(r[1]), "=r"(r[2]), "=r"(r[3]) : "r"(a));
}
__device__ __forceinline__ void mma16816(float c[4], const uint32_t a[4],
                                         uint32_t b0, uint32_t b1) {
    asm volatile(
        "mma.sync.aligned.m16n8k16.row.col.f32.f16.f16.f32 "
        "{%0,%1,%2,%3}, {%4,%5,%6,%7}, {%8,%9}, {%0,%1,%2,%3};"
        : "+f"(c[0]), "+f"(c[1]), "+f"(c[2]), "+f"(c[3])
        : "r"(a[0]), "r"(a[1]), "r"(a[2]), "r"(a[3]), "r"(b0), "r"(b1));
}
__device__ __forceinline__ uint32_t pack_h2(float a, float b) {
    __half2 h = __floats2half2_rn(a, b);
    return *reinterpret_cast<uint32_t*>(&h);
}
// exp2 of two fp32 values -> packed fp16x2 (single 2-wide MUFU)
__device__ __forceinline__ uint32_t exp2_h2(float a, float b) {
    uint32_t p = pack_h2(a, b);
    uint32_t r;
    asm("ex2.approx.f16x2 %0, %1;" : "=r"(r) : "r"(p));
    return r;
}

#define CP16(dst, src) \
    asm volatile("cp.async.cg.shared.global [%0], [%1], 16;" \
                 :: "r"(dst), "l"(src) : "memory")
#define CP_COMMIT() asm volatile("cp.async.commit_group;" ::: "memory")
#define CP_WAIT1()  asm volatile("cp.async.wait_group 1;" ::: "memory")
#define CP_WAIT2()  asm volatile("cp.async.wait_group 2;" ::: "memory")

// ---------------- fp32 -> fp16 conversions ----------------
__global__ __launch_bounds__(256) void convert_x_kernel(const float* __restrict__ x)
{
    size_t i = (size_t)blockIdx.x * 256 + threadIdx.x;
    float4 v = ((const float4*)x)[i];
    uint2 o;
    o.x = pack_h2(v.x, v.y);
    o.y = pack_h2(v.z, v.w);
    ((uint2*)g_x16)[i] = o;
}
__global__ __launch_bounds__(256) void convert_w_kernel(
    const float* __restrict__ Wk, const float* __restrict__ Wq,
    const float* __restrict__ Wv)
{
    const int sel = blockIdx.y;
    const float* W = (sel == 0) ? Wq : (sel == 1) ? Wk : Wv;
    size_t i = (size_t)blockIdx.x * 256 + threadIdx.x;
    float4 v = ((const float4*)W)[i];
    uint2 o;
    o.x = pack_h2(v.x, v.y);
    o.y = pack_h2(v.z, v.w);
    ((uint2*)g_w16[sel])[i] = o;
}

// ---------------- QKV projection: fp16 mma, 3-stage ring, 2 CTAs/SM ----------
#define PSTR   72
#define PARR   (128 * PSTR)            // elems per array
#define PSTAGE (2 * PARR)              // elems per stage (x, w)
#define P_SMEM (3 * PSTAGE * 2)        // bytes = 110592

__global__ __launch_bounds__(256, 2) void qkv_mma_kernel()
{
    extern __shared__ __half ps[];

    const int tid = threadIdx.x, lane = tid & 31, w = tid >> 5;
    const int sel = blockIdx.y;
    const int m0  = blockIdx.x * 128;
    const int wr0 = w * 16;

    const __half* xp = g_x16 + (size_t)m0 * C_;
    const __half* wp = g_w16[sel];

    const uint32_t base = smem_u32(ps);

    uint32_t cpo[4];
    int      go[4];
#pragma unroll
    for (int it = 0; it < 4; it++) {
        int i   = tid + it * 256;          // 1024 uint4 per array
        int row = i >> 3, c8 = (i & 7) * 8;
        cpo[it] = (uint32_t)(row * PSTR + c8) * 2;
        go[it]  = row * C_ + c8;
    }

    auto issue = [&](int kc, int s) {
        const int k0 = kc * 64;
        const uint32_t sb = base + (uint32_t)(s * PSTAGE) * 2;
#pragma unroll
        for (int it = 0; it < 4; it++) {
            const size_t g = (size_t)go[it] + k0;
            CP16(sb + cpo[it],                (const char*)(xp + g));
            CP16(sb + PARR * 2 + cpo[it],     (const char*)(wp + g));
        }
    };

    float of[16][4];
#pragma unroll
    for (int j = 0; j < 16; j++)
#pragma unroll
        for (int e = 0; e < 4; e++) of[j][e] = 0.f;

    const uint32_t a_off = (uint32_t)(wr0 + (lane & 15)) * (PSTR * 2) + (lane >> 4) * 16;
    const uint32_t b_off = (uint32_t)((lane & 7) + ((lane >> 4) & 1) * 8) * (PSTR * 2)
                         + ((lane >> 3) & 1) * 16;

    issue(0, 0);
    CP_COMMIT();

    const int NC = C_ / 64;   // 16
    for (int kc = 0; kc < NC; kc++) {
        if (kc + 1 < NC) issue(kc + 1, (kc + 1) % 3);
        CP_COMMIT();
        CP_WAIT1();
        __syncthreads();

        const uint32_t sb   = base + (uint32_t)((kc % 3) * PSTAGE) * 2;
        const uint32_t sx_b = sb;
        const uint32_t sw_b = sb + PARR * 2;

#pragma unroll
        for (int u = 0; u < 4; u++) {
            uint32_t ax[4];
            ldsm4(ax, sx_b + a_off + u * 32);
#pragma unroll
            for (int jp = 0; jp < 8; jp++) {
                uint32_t bh[4];
                ldsm4(bh, sw_b + b_off + (uint32_t)jp * 16 * (PSTR * 2) + u * 32);
                mma16816(of[2 * jp],     ax, bh[0], bh[1]);
                mma16816(of[2 * jp + 1], ax, bh[2], bh[3]);
            }
        }
        // no tail sync: 3-stage ring keeps write stage disjoint from any
        // stage readable by a warp that is at most one iteration behind.
    }

    // q scale folds softmax 1/sqrt(H) AND log2(e) (flash works in exp2 domain)
    const float scl = (sel == 0) ? (1.4426950408889634f * 0.08838834764831845f)
                                 : 1.0f;
    __half* op = (sel == 0) ? g_q16 : (sel == 1) ? g_k16 : g_v16;
#pragma unroll
    for (int j = 0; j < 16; j++)
#pragma unroll
        for (int i = 0; i < 2; i++) {
            const size_t row = (size_t)(m0 + wr0 + (lane >> 2) + 8 * i);
            const int col = 8 * j + (lane & 3) * 2;
            *(uint32_t*)&op[row * H_ + col] =
                pack_h2(of[j][2 * i] * scl, of[j][2 * i + 1] * scl);
        }
}

// ---------------- flash attention: fp16 mma, 4-stage KV ring, exp2 softmax ----
#define FSTR   136
#define FQ     (128 * FSTR)
#define FKV    (64 * FSTR)
#define FSTAGE (2 * FKV)                      // K + V
#define F_SMEM ((FQ + 4 * FSTAGE) * 2)        // 174080 B

__global__ __launch_bounds__(256) void flash_kernel(float* __restrict__ out)
{
    extern __shared__ __half fs[];
    __half* sq = fs;

    const int tid = threadIdx.x, lane = tid & 31, w = tid >> 5;
    const int b   = blockIdx.x;
    const int r0  = (gridDim.y - 1 - blockIdx.y) * 128;   // heavy rows first
    const int wr0 = w * 16;

    const uint32_t base   = smem_u32(fs);
    const uint32_t kvbase = base + (uint32_t)FQ * 2;

    uint32_t cpo[4];
    int      go[4];
#pragma unroll
    for (int it = 0; it < 4; it++) {
        int i   = tid + it * 256;            // 1024 uint4 per array
        int row = i >> 4, c8 = (i & 15) * 8;
        cpo[it] = (uint32_t)(row * FSTR + c8) * 2;
        go[it]  = row * H_ + c8;
    }

    const size_t bbase = (size_t)b * T_ * H_;
    auto issue = [&](int t, int s) {
        const size_t off = bbase + (size_t)t * 64 * H_;
        const __half* kp = g_k16 + off;
        const __half* vp = g_v16 + off;
        const uint32_t sb = kvbase + (uint32_t)(s * FSTAGE) * 2;
#pragma unroll
        for (int it = 0; it < 4; it++) {
            CP16(sb + cpo[it],             (const char*)(kp + go[it]));
            CP16(sb + FKV * 2 + cpo[it],   (const char*)(vp + go[it]));
        }
    };

    const int ntiles = r0 / 64 + 2;

    // prologue: 2 tiles in flight, then load Q
    issue(0, 0); CP_COMMIT();
    issue(1, 1); CP_COMMIT();

    const uint4* qp = (const uint4*)(g_q16 + bbase + (size_t)r0 * H_);
#pragma unroll
    for (int it = 0; it < 8; it++) {
        int i = tid + it * 256;               // 2048 uint4
        int row = i >> 4, c8 = (i & 15) * 8;
        *(uint4*)&sq[row * FSTR + c8] = qp[i];
    }
    __syncthreads();

    const uint32_t qa_off = (uint32_t)(wr0 + (lane & 15)) * (FSTR * 2) + (lane >> 4) * 16;
    const uint32_t kb_off = (uint32_t)((lane & 7) + ((lane >> 4) & 1) * 8) * (FSTR * 2)
                          + ((lane >> 3) & 1) * 16;
    const uint32_t vb_off = (uint32_t)((lane & 7) + ((lane >> 3) & 1) * 8) * (FSTR * 2)
                          + ((lane >> 4) & 1) * 16;

    uint32_t qf[8][4];
#pragma unroll
    for (int u = 0; u < 8; u++) ldsm4(qf[u], base + qa_off + u * 32);

    float of[16][4];
#pragma unroll
    for (int j = 0; j < 16; j++)
#pragma unroll
        for (int e = 0; e < 4; e++) of[j][e] = 0.f;
    float m_i[2] = {-1e30f, -1e30f}, l_i[2] = {0.f, 0.f};

    for (int t = 0; t < ntiles; t++) {
        const int s0 = t * 64;
        if (t + 2 < ntiles) issue(t + 2, (t + 2) & 3);
        CP_COMMIT();
        CP_WAIT2();
        __syncthreads();

        const uint32_t sb   = kvbase + (uint32_t)((t & 3) * FSTAGE) * 2;
        const uint32_t sk_b = sb;
        const uint32_t sv_b = sb + FKV * 2;

        // ---- S = Q K^T  (logits already in log2 domain via q scale) ----
        float sf[8][4];
#pragma unroll
        for (int j = 0; j < 8; j++)
#pragma unroll
            for (int e = 0; e < 4; e++) sf[j][e] = 0.f;

#pragma unroll
        for (int u = 0; u < 8; u++) {
#pragma unroll
            for (int jp = 0; jp < 4; jp++) {
                uint32_t bh[4];
                ldsm4(bh, sk_b + kb_off + (uint32_t)jp * 16 * (FSTR * 2) + u * 32);
                mma16816(sf[2 * jp],     qf[u], bh[0], bh[1]);
                mma16816(sf[2 * jp + 1], qf[u], bh[2], bh[3]);
            }
        }

        // ---- causal mask ----
        const int rowg0 = r0 + wr0 + (lane >> 2);
        if (s0 + 63 > rowg0) {
#pragma unroll
            for (int j = 0; j < 8; j++) {
                const int colg = s0 + 8 * j + (lane & 3) * 2;
#pragma unroll
                for (int i = 0; i < 2; i++) {
                    const int rg = rowg0 + 8 * i;
                    if (colg     > rg) sf[j][2 * i]     = -1e30f;
                    if (colg + 1 > rg) sf[j][2 * i + 1] = -1e30f;
                }
            }
        }

        // ---- online softmax (exp2 domain, 2-wide f16 EX2 -> packed P) ----
        uint32_t pf[8][2];
#pragma unroll
        for (int i = 0; i < 2; i++) {
            float mx = sf[0][2 * i];
#pragma unroll
            for (int j = 0; j < 8; j++) {
                mx = fmaxf(mx, sf[j][2 * i]);
                mx = fmaxf(mx, sf[j][2 * i + 1]);
            }
            mx = fmaxf(mx, __shfl_xor_sync(0xffffffffu, mx, 1));
            mx = fmaxf(mx, __shfl_xor_sync(0xffffffffu, mx, 2));
            const float mn  = fmaxf(m_i[i], mx);
            const float fac = exp2f(m_i[i] - mn);
            m_i[i] = mn;
            float rs = 0.f;
#pragma unroll
            for (int j = 0; j < 8; j++) {
                const uint32_t p2 = exp2_h2(sf[j][2 * i] - mn, sf[j][2 * i + 1] - mn);
                pf[j][i] = p2;
                const float2 pv = __half22float2(*reinterpret_cast<const __half2*>(&p2));
                rs += pv.x + pv.y;
            }
            rs += __shfl_xor_sync(0xffffffffu, rs, 1);
            rs += __shfl_xor_sync(0xffffffffu, rs, 2);
            l_i[i] = l_i[i] * fac + rs;
#pragma unroll
            for (int j = 0; j < 16; j++) {
                of[j][2 * i] *= fac; of[j][2 * i + 1] *= fac;
            }
        }

        // ---- O += P V ----
#pragma unroll
        for (int u = 0; u < 4; u++) {
            uint32_t ph[4];
            ph[0] = pf[2 * u][0];
            ph[1] = pf[2 * u][1];
            ph[2] = pf[2 * u + 1][0];
            ph[3] = pf[2 * u + 1][1];
#pragma unroll
            for (int jp = 0; jp < 8; jp++) {
                uint32_t vh[4];
                ldsm4t(vh, sv_b + vb_off + (uint32_t)u * 16 * (FSTR * 2) + jp * 32);
                mma16816(of[2 * jp],     ph, vh[0], vh[1]);
                mma16816(of[2 * jp + 1], ph, vh[2], vh[3]);
            }
        }
        // no tail sync: 4-stage ring makes the write stage disjoint from any
        // stage readable by a warp at most one iteration behind the top sync.
    }

    // ---- write O ----
    const float inv0 = 1.0f / l_i[0], inv1 = 1.0f / l_i[1];
#pragma unroll
    for (int j = 0; j < 16; j++)
#pragma unroll
        for (int i = 0; i < 2; i++) {
            const size_t row = (size_t)b * T_ + r0 + wr0 + (lane >> 2) + 8 * i;
            const int col = 8 * j + (lane & 3) * 2;
            const float inv = i ? inv1 : inv0;
            float2 v = make_float2(of[j][2 * i] * inv, of[j][2 * i + 1] * inv);
            *(float2*)&out[row * H_ + col] = v;
        }
}

// ---------------------------------------------------------------------------
extern "C" void kernel_launch(void* const* d_in, const int* in_sizes, int n_in,
                              void* d_out, int out_size)
{
    const float* x  = (const float*)d_in[0];
    const float* Wk = (const float*)d_in[1];
    const float* Wq = (const float*)d_in[2];
    const float* Wv = (const float*)d_in[3];
    float* out = (float*)d_out;

    cudaFuncSetAttribute(qkv_mma_kernel,
                         cudaFuncAttributeMaxDynamicSharedMemorySize, P_SMEM);
    cudaFuncSetAttribute(flash_kernel,
                         cudaFuncAttributeMaxDynamicSharedMemorySize, F_SMEM);

    convert_x_kernel<<<(M_ * (size_t)C_ / 4) / 256, 256>>>(x);
    convert_w_kernel<<<dim3((H_ * C_ / 4) / 256, 3, 1), 256>>>(Wk, Wq, Wv);
    qkv_mma_kernel<<<dim3(M_ / 128, 3, 1), 256, P_SMEM>>>();
    flash_kernel<<<dim3(B_, T_ / 128, 1), 256, F_SMEM>>>(out);
}